// round 11
// baseline (speedup 1.0000x reference)
#include <cuda_runtime.h>
#include <cstddef>
#include <cstdint>

#define NEGF (-1e20f)

constexpr int NA   = 512;
constexpr int NBC  = 1024;
constexpr int TPC  = 8;
constexpr int NTB  = 128;          // threads per batch (4 warps)
constexpr int NT   = 256;          // 2 batches per CTA
constexpr int WIN  = 8;
constexpr int NWINS = 80;          // 640 steps >= 639
constexpr int E_NEG = -(1 << 28);

constexpr int F_F4 = 2 * WIN * NTB * 2;   // 4096 f4 = 64KB (double-buffered W band)
constexpr int O_F4 = WIN * NTB * 2;       // 2048 f4 = 32KB (raw values)
constexpr int E_I  = WIN * NTB;           // 4KB (shared exponents)
constexpr int BATCH_B = F_F4 * 16 + O_F4 * 16 + E_I * 4 + 64;
constexpr size_t SMEM_B = 2 * (size_t)BATCH_B;

__device__ __forceinline__ float p2(int d) {
    int k = max(d + 127, 0);
    return __int_as_float(k << 23);
}
__device__ __forceinline__ void cpa16(uint32_t dst, const void* src) {
    asm volatile("cp.async.cg.shared.global [%0], [%1], 16;" :: "r"(dst), "l"(src));
}

__global__ void __launch_bounds__(NT, 1)
dtw_dual_kernel(const float* __restrict__ W, float* __restrict__ out) {
    extern __shared__ unsigned char sm[];
    const int bb   = threadIdx.x >> 7;    // batch within CTA (0/1)
    const int tb   = threadIdx.x & 127;   // thread within batch
    const int lane = tb & 31, wd = tb >> 5;

    unsigned char* base = sm + bb * BATCH_B;
    float4* F = (float4*)base;                              // [2][WIN][NTB][2]
    float4* O = F + F_F4;                                   // [WIN][NTB][2]
    int*    E = (int*)(O + O_F4);                           // [WIN][NTB]
    unsigned long long* bnd = (unsigned long long*)(E + E_I); // [2][4]

    const int b = blockIdx.x * 2 + bb;
    const float* Wb = W + (size_t)b * NA * NBC;
    float* Ob = out + (size_t)b * (NA + 1) * (NBC + 1);
    const uint32_t Fs = (uint32_t)__cvta_generic_to_shared(F);
    const int barid = 1 + bb;

    // ---- edge outputs (per batch) ----
    for (int k = tb; k <= NBC; k += NTB) Ob[k] = (k == 0) ? 0.0f : NEGF;
    for (int r = tb + 1; r <= NA; r += NTB) Ob[(size_t)r * (NBC + 1)] = NEGF;

    float tm[TPC];
    #pragma unroll
    for (int k = 0; k < TPC; ++k) tm[k] = 0.0f;
    int   te = E_NEG;
    float pm = 0.0f; int pe = E_NEG;

    const int rsub = lane >> 4;            // 2 rows per warp-iteration
    const int off  = (lane >> 1) & 7;      // 8 diagonal offsets
    const int h    = lane & 1;             // float4 half

    auto issue_fill = [&](int w) {
        if (w >= NWINS) return;
        const int S = WIN * w, p = w & 1;
        #pragma unroll 4
        for (int ri = wd * 2; ri < 135; ri += 8) {
            int r  = S - 127 + ri + rsub;
            int tt = S - r + off;                  // diag s = r+tt+1 in [S+1,S+8]
            if ((unsigned)r < (unsigned)NA && (unsigned)tt < 128u) {
                int sg = (r + tt + 1) & (WIN - 1);
                uint32_t dst = Fs + (uint32_t)((((p * WIN + sg) * NTB + tt) * 2 + h) * 16);
                cpa16(dst, Wb + (size_t)r * NBC + 8 * tt + 4 * h);
            }
        }
        asm volatile("cp.async.commit_group;" ::: "memory");
    };
    auto flush_win = [&](int w) {
        const int S = WIN * w;
        #pragma unroll 4
        for (int ri = wd * 2; ri < 135; ri += 8) {
            int i  = S - 126 + ri + rsub;
            int tt = S + 1 - i + off;              // diag s = i+tt in [S+1,S+8]
            if (i >= 1 && i <= NA && (unsigned)tt < 128u) {
                int sg = (i + tt) & (WIN - 1);
                float4 v = O[(sg * NTB + tt) * 2 + h];
                float eb = (float)E[sg * NTB + tt];
                float* g = Ob + (size_t)i * (NBC + 1) + 8 * tt + 4 * h + 1;
                g[0] = (__log2f(v.x) + eb) * 0.69314718056f;
                g[1] = (__log2f(v.y) + eb) * 0.69314718056f;
                g[2] = (__log2f(v.z) + eb) * 0.69314718056f;
                g[3] = (__log2f(v.w) + eb) * 0.69314718056f;
            }
        }
    };

    issue_fill(0);
    __syncthreads();   // last CTA-wide barrier; batches decouple after this

    for (int win = 0; win < NWINS; ++win) {
        const int S = WIN * win;
        asm volatile("cp.async.wait_group 0;" ::: "memory");
        asm volatile("bar.sync %0, %1;" :: "r"(barid), "r"(NTB) : "memory");
        issue_fill(win + 1);
        if (win > 0) flush_win(win - 1);
        asm volatile("bar.sync %0, %1;" :: "r"(barid), "r"(NTB) : "memory");

        #pragma unroll 1
        for (int q = 1; q <= WIN; ++q) {
            const int s = S + q;
            const int i = s - tb;
            const bool act = (unsigned)(i - 1) < (unsigned)NA;

            float lvm = __shfl_up_sync(0xFFFFFFFFu, tm[TPC - 1], 1);
            int   lve = __shfl_up_sync(0xFFFFFFFFu, te, 1);
            if (lane == 0 && wd > 0) {
                unsigned long long pk = bnd[(s & 1) * 4 + wd - 1];
                lvm = __uint_as_float((unsigned)pk);
                lve = (int)(pk >> 32);
            }
            if (tb == 0) { lvm = 0.0f; lve = E_NEG; }

            float dm = pm; int de = pe;
            if (i == 1) { dm = (tb == 0) ? 1.0f : 0.0f; de = (tb == 0) ? 0 : E_NEG; }
            pm = lvm; pe = lve;

            if (act) {
                const int sg = s & (WIN - 1);
                const int fb = ((win & 1) * WIN + sg) * NTB + tb;
                float4 fA = F[fb * 2];
                float4 fB = F[fb * 2 + 1];
                float wv[TPC] = {fA.x, fA.y, fA.z, fA.w, fB.x, fB.y, fB.z, fB.w};

                int e_base = max(te, max(lve, de));
                float pt = p2(te  - e_base);
                float pl = p2(lve - e_base);
                float pd = p2(de  - e_base);

                float v[TPC];
                float leftm = fmaf(tm[0], pt, fmaf(dm, pd, lvm * pl));
                v[0] = fmaxf(leftm * __expf(wv[0]), 1e-35f);
                leftm = v[0];
                #pragma unroll
                for (int k = 1; k < TPC; ++k) {
                    float sk = fmaf(tm[k] + tm[k - 1], pt, leftm);
                    v[k] = fmaxf(sk * __expf(wv[k]), 1e-35f);
                    leftm = v[k];
                }

                int ob = (sg * NTB + tb) * 2;
                O[ob]     = make_float4(v[0], v[1], v[2], v[3]);
                O[ob + 1] = make_float4(v[4], v[5], v[6], v[7]);
                E[sg * NTB + tb] = e_base;

                float vmax = fmaxf(fmaxf(fmaxf(v[0], v[1]), fmaxf(v[2], v[3])),
                                   fmaxf(fmaxf(v[4], v[5]), fmaxf(v[6], v[7])));
                int sh = (__float_as_int(vmax) >> 23) - 127;
                float sc = p2(-sh);
                #pragma unroll
                for (int k = 0; k < TPC; ++k) tm[k] = v[k] * sc;
                te = e_base + sh;

                if (lane == 31)
                    bnd[((s + 1) & 1) * 4 + wd] =
                        ((unsigned long long)(unsigned)te << 32) |
                        (unsigned long long)__float_as_uint(tm[TPC - 1]);
            }
            asm volatile("bar.sync %0, %1;" :: "r"(barid), "r"(NTB) : "memory");
        }
    }

    flush_win(NWINS - 1);
}

extern "C" void kernel_launch(void* const* d_in, const int* in_sizes, int n_in,
                              void* d_out, int out_size) {
    const float* W = (const float*)d_in[0];
    float* out = (float*)d_out;
    cudaFuncSetAttribute(dtw_dual_kernel,
                         cudaFuncAttributeMaxDynamicSharedMemorySize,
                         (int)SMEM_B);
    dtw_dual_kernel<<<16, NT, SMEM_B>>>(W, out);
}